// round 1
// baseline (speedup 1.0000x reference)
#include <cuda_runtime.h>

// Problem constants: x:(8,8,512,64) f32, a:(64,1) f32 -> out:(8,512,512) f32
// S[n,i,j] = E[n,i,j] / sum_i' E[n,i',j],  E = exp(relu(sum_f a[f]*|xm[n,i,f]-xm[n,j,f]|))
// xm = x[:, 4, :, :]

#define VV 512
#define FF 64
#define JT 32          // j-tile per block
#define XI_STRIDE 68   // pad: float4-aligned rows, conflict-free A reads
#define XJ_STRIDE 65   // pad: conflict-free B reads
#define THREADS 512

// dynamic smem layout (floats):
//   sxi  : VV*XI_STRIDE = 34816
//   sxj  : JT*XJ_STRIDE = 2080
//   sa   : 64
//   red  : 64*JT       = 2048
//   sinv : JT          = 32
#define SMEM_FLOATS (VV*XI_STRIDE + JT*XJ_STRIDE + FF + 64*JT + JT)

__global__ __launch_bounds__(THREADS) void graph_learn_kernel(
    const float* __restrict__ x, const float* __restrict__ a,
    float* __restrict__ out)
{
    extern __shared__ float smem[];
    float* sxi  = smem;
    float* sxj  = sxi + VV * XI_STRIDE;
    float* sa   = sxj + JT * XJ_STRIDE;
    float* red  = sa + FF;
    float* sinv = red + 64 * JT;

    const int n   = blockIdx.y;
    const int j0  = blockIdx.x * JT;
    const int tid = threadIdx.x;

    // xm[n] base: x + ((n*8 + 4) * 512) * 64
    const float* xm = x + ((size_t)(n * 8 + 4)) * VV * FF;

    // ---- stage xm[n] (all 512 rows) into padded smem ----
    const float4* xg = (const float4*)xm;
    #pragma unroll
    for (int k = 0; k < (VV * FF / 4) / THREADS; k++) {      // 16 iterations
        int g   = tid + k * THREADS;                          // float4 index
        int row = g >> 4, f4 = g & 15;
        float4 v = xg[g];
        float* d = sxi + row * XI_STRIDE + f4 * 4;
        d[0] = v.x; d[1] = v.y; d[2] = v.z; d[3] = v.w;
    }
    // ---- stage the 32-row j-tile ----
    const float4* xjg = (const float4*)(xm + (size_t)j0 * FF);
    if (tid < JT * FF / 4) {                                  // 512 float4s
        int row = tid >> 4, f4 = tid & 15;
        float4 v = xjg[tid];
        float* d = sxj + row * XJ_STRIDE + f4 * 4;
        d[0] = v.x; d[1] = v.y; d[2] = v.z; d[3] = v.w;
    }
    if (tid < FF) sa[tid] = a[tid];
    __syncthreads();

    const int tx = tid & 7;    // 8 groups across j (4 j each)
    const int ty = tid >> 3;   // 0..63 across i (8 i each, strided by 64)

    float acc[8][4];
    #pragma unroll
    for (int r = 0; r < 8; r++)
        #pragma unroll
        for (int c = 0; c < 4; c++) acc[r][c] = 0.f;

    const float* bj = sxj + (tx * 4) * XJ_STRIDE;

    #pragma unroll 4
    for (int f = 0; f < FF; f++) {
        float av = sa[f];
        float B0 = bj[0 * XJ_STRIDE + f];
        float B1 = bj[1 * XJ_STRIDE + f];
        float B2 = bj[2 * XJ_STRIDE + f];
        float B3 = bj[3 * XJ_STRIDE + f];
        #pragma unroll
        for (int r = 0; r < 8; r++) {
            float A = sxi[(r * 64 + ty) * XI_STRIDE + f];
            acc[r][0] += av * fabsf(A - B0);
            acc[r][1] += av * fabsf(A - B1);
            acc[r][2] += av * fabsf(A - B2);
            acc[r][3] += av * fabsf(A - B3);
        }
    }

    // ---- exp(relu) + per-thread partial column sums ----
    float psum[4] = {0.f, 0.f, 0.f, 0.f};
    #pragma unroll
    for (int r = 0; r < 8; r++)
        #pragma unroll
        for (int c = 0; c < 4; c++) {
            float e = __expf(fmaxf(acc[r][c], 0.f));
            acc[r][c] = e;
            psum[c] += e;
        }
    #pragma unroll
    for (int c = 0; c < 4; c++) red[ty * JT + tx * 4 + c] = psum[c];
    __syncthreads();

    // ---- column reduce over the 64 ty-partials, store reciprocal ----
    if (tid < JT) {
        float s = 0.f;
        #pragma unroll
        for (int t = 0; t < 64; t++) s += red[t * JT + tid];
        sinv[tid] = 1.0f / s;
    }
    __syncthreads();

    float inv0 = sinv[tx * 4 + 0];
    float inv1 = sinv[tx * 4 + 1];
    float inv2 = sinv[tx * 4 + 2];
    float inv3 = sinv[tx * 4 + 3];

    float* outn = out + (size_t)n * VV * VV + j0;
    #pragma unroll
    for (int r = 0; r < 8; r++) {
        int i = r * 64 + ty;
        float4 v;
        v.x = acc[r][0] * inv0;
        v.y = acc[r][1] * inv1;
        v.z = acc[r][2] * inv2;
        v.w = acc[r][3] * inv3;
        *(float4*)(outn + (size_t)i * VV + tx * 4) = v;
    }
}

extern "C" void kernel_launch(void* const* d_in, const int* in_sizes, int n_in,
                              void* d_out, int out_size)
{
    const float* x = (const float*)d_in[0];
    const float* a = (const float*)d_in[1];
    float* out     = (float*)d_out;

    const size_t smem_bytes = (size_t)SMEM_FLOATS * sizeof(float);  // 156,160 B
    cudaFuncSetAttribute(graph_learn_kernel,
                         cudaFuncAttributeMaxDynamicSharedMemorySize,
                         (int)smem_bytes);

    dim3 grid(VV / JT, 8);   // (16 j-tiles, 8 batches) = 128 blocks
    graph_learn_kernel<<<grid, THREADS, smem_bytes>>>(x, a, out);
}